// round 4
// baseline (speedup 1.0000x reference)
#include <cuda_runtime.h>
#include <cstdint>

#define B_SZ   4096
#define T_SZ   2
#define L_SZ   3
#define D_IN   768
#define D_SAE  16384
#define TOPK   64
#define KDIM   (L_SZ * D_IN)          // 2304
#define TLD    (T_SZ * L_SZ * D_IN)   // 4608

// ---------------- scratch (static device memory; no runtime alloc) ----------
__device__ float g_xsum[(size_t)B_SZ * KDIM];     // 37.7 MB
__device__ float g_pre [(size_t)B_SZ * D_SAE];    // 268 MB
__device__ int   g_tidx[B_SZ * TOPK];
__device__ float g_tval[B_SZ * TOPK];

// ---------------- kernel 1: fold t-dim of x, zero the loss ------------------
__global__ void xsum_kernel(const float* __restrict__ x, float* __restrict__ loss)
{
    int idx = blockIdx.x * blockDim.x + threadIdx.x;
    if (idx == 0) *loss = 0.0f;
    if (idx < B_SZ * KDIM) {
        int b = idx / KDIM;
        int r = idx - b * KDIM;                  // r = l*768 + d
        const float* xb = x + (size_t)b * TLD;   // layout (T, L, D): t-stride = KDIM
        g_xsum[idx] = xb[r] + xb[KDIM + r];
    }
}

// ---------------- kernel 2: fp32 SGEMM  pre = xsum @ Wenc + benc ------------
// A: g_xsum (4096 x 2304), B: Wenc viewed (2304 x 16384), C: g_pre (4096 x 16384)
// 128x128 tile, BK=16, 256 threads, 8x8 microtile. Two-level accumulation
// (fold every 18 K-tiles = 288 K) to keep summation error ~1.5e-6 abs.
__global__ __launch_bounds__(256, 1) void encode_gemm(
    const float* __restrict__ Bw, const float* __restrict__ bias)
{
    __shared__ float As[16][128];
    __shared__ float Bs[16][128];

    const int tid   = threadIdx.x;
    const int tx    = tid & 15;       // 0..15 -> 8 columns each
    const int ty    = tid >> 4;       // 0..15 -> 8 rows each
    const int mBase = blockIdx.y * 128;
    const int nBase = blockIdx.x * 128;

    const int aRow = tid >> 1;        // 0..127
    const int aCol = (tid & 1) * 8;   // 0 or 8
    const int bRow = tid >> 5;        // 0..7
    const int bCol = (tid & 31) * 4;  // 0..124

    float c [8][8];
    float cm[8][8];
#pragma unroll
    for (int i = 0; i < 8; i++)
#pragma unroll
        for (int j = 0; j < 8; j++) { c[i][j] = 0.0f; cm[i][j] = 0.0f; }

    const float* Aptr = g_xsum + (size_t)(mBase + aRow) * KDIM;

    const int NT = KDIM / 16;  // 144
    for (int kt = 0; kt < NT; ++kt) {
        const int k0 = kt * 16;
        float4 av0 = *(const float4*)(Aptr + k0 + aCol);
        float4 av1 = *(const float4*)(Aptr + k0 + aCol + 4);
        float4 bv0 = *(const float4*)(Bw + (size_t)(k0 + bRow) * D_SAE + nBase + bCol);
        float4 bv1 = *(const float4*)(Bw + (size_t)(k0 + bRow + 8) * D_SAE + nBase + bCol);

        __syncthreads();
        As[aCol + 0][aRow] = av0.x;
        As[aCol + 1][aRow] = av0.y;
        As[aCol + 2][aRow] = av0.z;
        As[aCol + 3][aRow] = av0.w;
        As[aCol + 4][aRow] = av1.x;
        As[aCol + 5][aRow] = av1.y;
        As[aCol + 6][aRow] = av1.z;
        As[aCol + 7][aRow] = av1.w;
        *(float4*)&Bs[bRow][bCol]     = bv0;
        *(float4*)&Bs[bRow + 8][bCol] = bv1;
        __syncthreads();

#pragma unroll
        for (int kk = 0; kk < 16; ++kk) {
            float a[8], b[8];
#pragma unroll
            for (int i = 0; i < 8; i++) a[i] = As[kk][ty * 8 + i];
            float4 b0 = *(float4*)&Bs[kk][tx * 8];
            float4 b1 = *(float4*)&Bs[kk][tx * 8 + 4];
            b[0] = b0.x; b[1] = b0.y; b[2] = b0.z; b[3] = b0.w;
            b[4] = b1.x; b[5] = b1.y; b[6] = b1.z; b[7] = b1.w;
#pragma unroll
            for (int i = 0; i < 8; i++)
#pragma unroll
                for (int j = 0; j < 8; j++)
                    c[i][j] = fmaf(a[i], b[j], c[i][j]);
        }

        if ((kt % 18) == 17) {   // 144 = 18*8 -> exactly 8 folds, none left over
#pragma unroll
            for (int i = 0; i < 8; i++)
#pragma unroll
                for (int j = 0; j < 8; j++) { cm[i][j] += c[i][j]; c[i][j] = 0.0f; }
        }
    }

#pragma unroll
    for (int i = 0; i < 8; i++) {
        const int m = mBase + ty * 8 + i;
        float* Crow = g_pre + (size_t)m * D_SAE + nBase + tx * 8;
#pragma unroll
        for (int j = 0; j < 8; j++)
            Crow[j] = cm[i][j] + bias[nBase + tx * 8 + j];
    }
}

// ---------------- kernel 3: exact top-64 per row (radix select) -------------
__device__ __forceinline__ unsigned int fmap(float f)
{
    unsigned int u = __float_as_uint(f);
    return (u & 0x80000000u) ? ~u : (u | 0x80000000u);
}
__device__ __forceinline__ float finv(unsigned int u)
{
    return (u & 0x80000000u) ? __uint_as_float(u ^ 0x80000000u)
                             : __uint_as_float(~u);
}

__global__ void topk_kernel(float* __restrict__ z)
{
    __shared__ int hist[256];
    __shared__ unsigned int s_prefix;
    __shared__ int s_need, s_tie, s_slot;

    const int b = blockIdx.x;
    const float* row = g_pre + (size_t)b * D_SAE;

    if (threadIdx.x == 0) { s_prefix = 0u; s_need = TOPK; s_tie = 0; s_slot = 0; }
    __syncthreads();

    for (int p = 3; p >= 0; --p) {
        for (int i = threadIdx.x; i < 256; i += blockDim.x) hist[i] = 0;
        __syncthreads();
        const unsigned int himask = (p == 3) ? 0u : (0xFFFFFFFFu << (8 * (p + 1)));
        const unsigned int prefix = s_prefix;
        for (int s = threadIdx.x; s < D_SAE; s += blockDim.x) {
            unsigned int u = fmap(row[s]);
            if ((u & himask) == prefix)
                atomicAdd(&hist[(u >> (8 * p)) & 0xFF], 1);
        }
        __syncthreads();
        if (threadIdx.x == 0) {
            int need = s_need, cum = 0, bsel = 0;
            for (int bb = 255; bb >= 0; --bb) {
                if (cum + hist[bb] >= need) { bsel = bb; break; }
                cum += hist[bb];
            }
            s_prefix = prefix | ((unsigned int)bsel << (8 * p));
            s_need   = need - cum;        // how many ties at the threshold value
        }
        __syncthreads();
    }

    const unsigned int T = s_prefix;
    const int tie_need   = s_need;
    float* zrow = z + (size_t)b * D_SAE;

    for (int s = threadIdx.x; s < D_SAE; s += blockDim.x) {
        unsigned int u = fmap(row[s]);
        bool sel = (u > T);
        if (!sel && u == T) {
            if (atomicAdd(&s_tie, 1) < tie_need) sel = true;
        }
        float zv = 0.0f;
        if (sel) {
            zv = fmaxf(finv(u), 0.0f);
            int slot = atomicAdd(&s_slot, 1);
            g_tidx[b * TOPK + slot] = s;
            g_tval[b * TOPK + slot] = zv;
        }
        zrow[s] = zv;
    }
}

// ---------------- kernel 4: sparse decode + x_hat + loss --------------------
__global__ __launch_bounds__(512) void decode_kernel(
    const float* __restrict__ Wdec, const float* __restrict__ bdec,
    const float* __restrict__ x,
    float* __restrict__ xhat, float* __restrict__ loss)
{
    const int b = blockIdx.x;
    const int t = threadIdx.x;           // 512 threads, 9 elems each (4608)

    float acc[9];
#pragma unroll
    for (int i = 0; i < 9; i++) acc[i] = bdec[t + i * 512];

    const int*   idxp = g_tidx + b * TOPK;
    const float* valp = g_tval + b * TOPK;

    for (int k = 0; k < TOPK; k++) {
        const float v = valp[k];
        const float* w = Wdec + (size_t)idxp[k] * TLD;
#pragma unroll
        for (int i = 0; i < 9; i++) acc[i] = fmaf(v, w[t + i * 512], acc[i]);
    }

    const float* xb = x + (size_t)b * TLD;
    float* xh = xhat + (size_t)b * TLD;
    float sse = 0.0f;
#pragma unroll
    for (int i = 0; i < 9; i++) {
        const float d = acc[i] - xb[t + i * 512];
        sse += d * d;
        xh[t + i * 512] = acc[i];
    }

    __shared__ float red[512];
    red[t] = sse;
    __syncthreads();
    for (int st = 256; st > 0; st >>= 1) {
        if (t < st) red[t] += red[t + st];
        __syncthreads();
    }
    if (t == 0)
        atomicAdd(loss, red[0] * (1.0f / (float)(B_SZ * T_SZ * L_SZ)));
}

// ---------------- launch ----------------------------------------------------
extern "C" void kernel_launch(void* const* d_in, const int* in_sizes, int n_in,
                              void* d_out, int out_size)
{
    const float* x    = (const float*)d_in[0];
    const float* Wenc = (const float*)d_in[1];
    const float* benc = (const float*)d_in[2];
    const float* Wdec = (const float*)d_in[3];
    const float* bdec = (const float*)d_in[4];

    float* out  = (float*)d_out;
    float* loss = out;                                   // [0]
    float* xhat = out + 1;                               // [1 .. 1+B*TLD)
    float* z    = out + 1 + (size_t)B_SZ * TLD;          // [.. +B*D_SAE)

    // 1) fold t + zero loss
    {
        const int n = B_SZ * KDIM;
        xsum_kernel<<<(n + 255) / 256, 256>>>(x, loss);
    }
    // 2) encode GEMM
    {
        dim3 grid(D_SAE / 128, B_SZ / 128);   // (128, 32)
        encode_gemm<<<grid, 256>>>(Wenc, benc);
    }
    // 3) top-64 select + dense z
    topk_kernel<<<B_SZ, 256>>>(z);
    // 4) sparse decode + loss
    decode_kernel<<<B_SZ, 512>>>(Wdec, bdec, x, xhat, loss);
}

// round 7
// speedup vs baseline: 1.6314x; 1.6314x over previous
#include <cuda_runtime.h>
#include <cstdint>

#define B_SZ   4096
#define T_SZ   2
#define L_SZ   3
#define D_IN   768
#define D_SAE  16384
#define TOPK   64
#define KDIM   (L_SZ * D_IN)          // 2304
#define TLD    (T_SZ * L_SZ * D_IN)   // 4608

// ---------------- scratch (static device memory; no runtime alloc) ----------
__device__ float g_xsum[(size_t)B_SZ * KDIM];    // 37.7 MB  exact fold, [b][k]
__device__ float g_Ah[(size_t)KDIM * B_SZ];      // 37.7 MB  A hi, [k][m]
__device__ float g_Al[(size_t)KDIM * B_SZ];      // 37.7 MB  A lo, [k][m]
__device__ float g_Bh[(size_t)KDIM * D_SAE];     // 151 MB   B hi, [k][n]
__device__ float g_Bl[(size_t)KDIM * D_SAE];     // 151 MB   B lo, [k][n]
__device__ float g_pre[(size_t)B_SZ * D_SAE];    // 268 MB
__device__ unsigned int g_thr[B_SZ];
__device__ int   g_tidx[B_SZ * TOPK];
__device__ float g_tval[B_SZ * TOPK];

// ---------------- helpers ---------------------------------------------------
__device__ __forceinline__ float tf32_rna(float x) {
    uint32_t r;
    asm("cvt.rna.tf32.f32 %0, %1;" : "=r"(r) : "f"(x));
    return __uint_as_float(r);
}
__device__ __forceinline__ uint32_t smem_u32(const void* p) {
    uint32_t a;
    asm("{ .reg .u64 t; cvta.to.shared.u64 t, %1; cvt.u32.u64 %0, t; }" : "=r"(a) : "l"(p));
    return a;
}
#define CP_ASYNC16(sdst, gsrc) \
    asm volatile("cp.async.cg.shared.global [%0], [%1], 16;" :: "r"(sdst), "l"(gsrc))
#define CP_COMMIT()  asm volatile("cp.async.commit_group;")
#define CP_WAIT1()   asm volatile("cp.async.wait_group 1;")
#define CP_WAIT0()   asm volatile("cp.async.wait_group 0;")

#define MMA_TF32(c, a, b) \
    asm volatile("mma.sync.aligned.m16n8k8.row.col.f32.tf32.tf32.f32 " \
        "{%0,%1,%2,%3},{%4,%5,%6,%7},{%8,%9},{%0,%1,%2,%3};" \
        : "+f"((c)[0]), "+f"((c)[1]), "+f"((c)[2]), "+f"((c)[3]) \
        : "r"((a)[0]), "r"((a)[1]), "r"((a)[2]), "r"((a)[3]), \
          "r"((b)[0]), "r"((b)[1]))

// ---------------- kernel 0: split W_enc -> Bh/Bl ([k][n], natural layout) ---
__global__ __launch_bounds__(256) void wsplit_kernel(const float* __restrict__ W,
                                                     float* __restrict__ loss)
{
    const size_t i0 = (size_t)blockIdx.x * 256 + threadIdx.x;
    if (i0 == 0) *loss = 0.0f;
    const size_t N4 = (size_t)KDIM * D_SAE / 4;
    const float4* W4  = (const float4*)W;
    float4* Bh4 = (float4*)g_Bh;
    float4* Bl4 = (float4*)g_Bl;
    const size_t stride = (size_t)gridDim.x * 256;
    for (size_t i = i0; i < N4; i += stride) {
        float4 v = W4[i];
        float4 h, l;
        h.x = tf32_rna(v.x); l.x = tf32_rna(v.x - h.x);
        h.y = tf32_rna(v.y); l.y = tf32_rna(v.y - h.y);
        h.z = tf32_rna(v.z); l.z = tf32_rna(v.z - h.z);
        h.w = tf32_rna(v.w); l.w = tf32_rna(v.w - h.w);
        Bh4[i] = h; Bl4[i] = l;
    }
}

// ---------------- kernel 1: fold t, split, transpose -> Ah/Al [k][m] --------
// Also stores the exact fp32 fold g_xsum[b][k] (coalesced in load phase).
__global__ __launch_bounds__(256) void xsum_split_kernel(const float* __restrict__ x)
{
    __shared__ float tile[32][33];
    const int kb = blockIdx.x * 32;        // 72 blocks
    const int bb = blockIdx.y * 32;        // 128 blocks
    const int tx = threadIdx.x & 31;
    const int ty = threadIdx.x >> 5;       // 0..7
#pragma unroll
    for (int j = 0; j < 4; j++) {
        const int b = bb + ty + j * 8;
        const float* xb = x + (size_t)b * TLD + kb + tx;   // k contiguous
        const float v = xb[0] + xb[KDIM];                  // fold t
        tile[ty + j * 8][tx] = v;
        g_xsum[(size_t)b * KDIM + kb + tx] = v;
    }
    __syncthreads();
#pragma unroll
    for (int j = 0; j < 4; j++) {
        const int k = kb + ty + j * 8;
        const float v = tile[tx][ty + j * 8];
        const float h = tf32_rna(v);
        const float l = tf32_rna(v - h);
        const size_t o = (size_t)k * B_SZ + bb + tx;
        g_Ah[o] = h; g_Al[o] = l;
    }
}

// ---------------- kernel 2: 3xTF32 mma.sync GEMM ----------------------------
#define BM 128
#define BN 256
#define BK 16
#define NKT (KDIM / BK)                  // 144
#define A_PAD 132
#define B_PAD 260
#define SZ_A (BK * A_PAD)
#define SZ_B (BK * B_PAD)
#define STAGE_F (2 * SZ_A + 2 * SZ_B)
#define SMEM_BYTES (2 * STAGE_F * 4)     // 100352 B

__global__ __launch_bounds__(256, 1) void encode_gemm_mma(const float* __restrict__ bias)
{
    extern __shared__ float sm[];
    const uint32_t sb = smem_u32(sm);

    const int tid  = threadIdx.x;
    const int wid  = tid >> 5;
    const int lane = tid & 31;
    const int gid  = lane >> 2;
    const int tg   = lane & 3;
    const int mBase = blockIdx.x * BM;
    const int nBase = blockIdx.y * BN;
    const int wM = (wid & 1) * 64;
    const int wN = (wid >> 1) * 64;

    const int aRow  = tid >> 5;
    const int aCol4 = (tid & 31) * 4;
    const int bRow  = tid >> 6;
    const int bCol4 = (tid & 63) * 4;

#define ISSUE_STAGE(kt, buf)                                                          \
    do {                                                                              \
        const int _k0 = (kt) * BK;                                                    \
        const uint32_t _sf = sb + (buf) * (STAGE_F * 4);                              \
        _Pragma("unroll")                                                             \
        for (int p = 0; p < 2; p++) {                                                 \
            const int r = aRow + p * 8;                                               \
            const size_t go = (size_t)(_k0 + r) * B_SZ + mBase + aCol4;               \
            const uint32_t so = _sf + (r * A_PAD + aCol4) * 4;                        \
            CP_ASYNC16(so,            g_Ah + go);                                     \
            CP_ASYNC16(so + SZ_A * 4, g_Al + go);                                     \
        }                                                                             \
        _Pragma("unroll")                                                             \
        for (int p = 0; p < 4; p++) {                                                 \
            const int r = bRow + p * 4;                                               \
            const size_t go = (size_t)(_k0 + r) * D_SAE + nBase + bCol4;              \
            const uint32_t so = _sf + (2 * SZ_A + r * B_PAD + bCol4) * 4;             \
            CP_ASYNC16(so,            g_Bh + go);                                     \
            CP_ASYNC16(so + SZ_B * 4, g_Bl + go);                                     \
        }                                                                             \
    } while (0)

    float acc[4][8][4];
#pragma unroll
    for (int i = 0; i < 4; i++)
#pragma unroll
        for (int j = 0; j < 8; j++)
#pragma unroll
            for (int q = 0; q < 4; q++) acc[i][j][q] = 0.0f;

    ISSUE_STAGE(0, 0);
    CP_COMMIT();

    for (int kt = 0; kt < NKT; ++kt) {
        if (kt + 1 < NKT) {
            ISSUE_STAGE(kt + 1, (kt + 1) & 1);
            CP_COMMIT();
            CP_WAIT1();
        } else {
            CP_WAIT0();
        }
        __syncthreads();

        const uint32_t* sAh = (const uint32_t*)(sm + (kt & 1) * STAGE_F);
        const uint32_t* sAl = sAh + SZ_A;
        const uint32_t* sBh = sAh + 2 * SZ_A;
        const uint32_t* sBl = sBh + SZ_B;

#pragma unroll
        for (int jj = 0; jj < 2; jj++) {
            const int k0 = jj * 8;
            const int krA0 = (k0 + tg) * A_PAD;
            const int krA1 = (k0 + tg + 4) * A_PAD;
            const int krB0 = (k0 + tg) * B_PAD;
            const int krB1 = (k0 + tg + 4) * B_PAD;

            uint32_t ah[4][4], bh[8][2];
#pragma unroll
            for (int mf = 0; mf < 4; mf++) {
                const int m0 = wM + mf * 16 + gid;
                ah[mf][0] = sAh[krA0 + m0];
                ah[mf][1] = sAh[krA0 + m0 + 8];
                ah[mf][2] = sAh[krA1 + m0];
                ah[mf][3] = sAh[krA1 + m0 + 8];
            }
#pragma unroll
            for (int nf = 0; nf < 8; nf++) {
                const int n0 = wN + nf * 8 + gid;
                bh[nf][0] = sBh[krB0 + n0];
                bh[nf][1] = sBh[krB1 + n0];
            }
#pragma unroll
            for (int mf = 0; mf < 4; mf++)
#pragma unroll
                for (int nf = 0; nf < 8; nf++)
                    MMA_TF32(acc[mf][nf], ah[mf], bh[nf]);

            uint32_t al[4][4];
#pragma unroll
            for (int mf = 0; mf < 4; mf++) {
                const int m0 = wM + mf * 16 + gid;
                al[mf][0] = sAl[krA0 + m0];
                al[mf][1] = sAl[krA0 + m0 + 8];
                al[mf][2] = sAl[krA1 + m0];
                al[mf][3] = sAl[krA1 + m0 + 8];
            }
#pragma unroll
            for (int mf = 0; mf < 4; mf++)
#pragma unroll
                for (int nf = 0; nf < 8; nf++)
                    MMA_TF32(acc[mf][nf], al[mf], bh[nf]);

            uint32_t bl[8][2];
#pragma unroll
            for (int nf = 0; nf < 8; nf++) {
                const int n0 = wN + nf * 8 + gid;
                bl[nf][0] = sBl[krB0 + n0];
                bl[nf][1] = sBl[krB1 + n0];
            }
#pragma unroll
            for (int mf = 0; mf < 4; mf++)
#pragma unroll
                for (int nf = 0; nf < 8; nf++)
                    MMA_TF32(acc[mf][nf], ah[mf], bl[nf]);
        }
        __syncthreads();
    }

    float2 bv[8];
#pragma unroll
    for (int nf = 0; nf < 8; nf++)
        bv[nf] = *(const float2*)(bias + nBase + wN + nf * 8 + tg * 2);

#pragma unroll
    for (int mf = 0; mf < 4; mf++) {
        const int r0 = mBase + wM + mf * 16 + gid;
#pragma unroll
        for (int nf = 0; nf < 8; nf++) {
            const int col = nBase + wN + nf * 8 + tg * 2;
            float2 v0, v1;
            v0.x = acc[mf][nf][0] + bv[nf].x;
            v0.y = acc[mf][nf][1] + bv[nf].y;
            v1.x = acc[mf][nf][2] + bv[nf].x;
            v1.y = acc[mf][nf][3] + bv[nf].y;
            *(float2*)(g_pre + (size_t)r0 * D_SAE + col)       = v0;
            *(float2*)(g_pre + (size_t)(r0 + 8) * D_SAE + col) = v1;
        }
    }
}

// ---------------- kernel 3: radix threshold (64th largest, exact) -----------
__device__ __forceinline__ unsigned int fmap(float f)
{
    unsigned int u = __float_as_uint(f);
    return (u & 0x80000000u) ? ~u : (u | 0x80000000u);
}
__device__ __forceinline__ float finv(unsigned int u)
{
    return (u & 0x80000000u) ? __uint_as_float(u ^ 0x80000000u)
                             : __uint_as_float(~u);
}

__global__ void thresh_kernel()
{
    __shared__ int hist[256];
    __shared__ unsigned int s_prefix;
    __shared__ int s_need;

    const int b = blockIdx.x;
    const float* row = g_pre + (size_t)b * D_SAE;

    if (threadIdx.x == 0) { s_prefix = 0u; s_need = TOPK; }
    __syncthreads();

    for (int p = 3; p >= 0; --p) {
        for (int i = threadIdx.x; i < 256; i += blockDim.x) hist[i] = 0;
        __syncthreads();
        const unsigned int himask = (p == 3) ? 0u : (0xFFFFFFFFu << (8 * (p + 1)));
        const unsigned int prefix = s_prefix;
        for (int s = threadIdx.x; s < D_SAE; s += blockDim.x) {
            unsigned int u = fmap(row[s]);
            if ((u & himask) == prefix)
                atomicAdd(&hist[(u >> (8 * p)) & 0xFF], 1);
        }
        __syncthreads();
        if (threadIdx.x == 0) {
            int need = s_need, cum = 0, bsel = 0;
            for (int bb = 255; bb >= 0; --bb) {
                if (cum + hist[bb] >= need) { bsel = bb; break; }
                cum += hist[bb];
            }
            s_prefix = prefix | ((unsigned int)bsel << (8 * p));
            s_need   = need - cum;
        }
        __syncthreads();
    }
    if (threadIdx.x == 0) g_thr[b] = s_prefix;
}

// ---------------- kernel 4: select with exact fp64 boundary re-rank ---------
__global__ __launch_bounds__(256) void select_kernel(
    const float* __restrict__ Wenc, const float* __restrict__ benc,
    float* __restrict__ z)
{
    __shared__ float  s_x[KDIM];
    __shared__ double s_red[256];
    __shared__ double s_exact[128];
    __shared__ int    s_bidx[128];
    __shared__ int    s_nb, s_slot;

    const int b   = blockIdx.x;
    const int tid = threadIdx.x;
    const float* row = g_pre + (size_t)b * D_SAE;
    float* zrow = z + (size_t)b * D_SAE;

    if (tid == 0) { s_nb = 0; s_slot = 0; }
    __syncthreads();

    const float vT  = finv(g_thr[b]);
    const float dlt = 1e-3f;

    // phase 1: classify; write z for safe/out; collect boundary candidates
    for (int s = tid; s < D_SAE; s += 256) {
        const float v = row[s];
        float zv = 0.0f;
        if (v > vT + dlt) {
            zv = fmaxf(v, 0.0f);
            int slot = atomicAdd(&s_slot, 1);
            if (slot < TOPK) { g_tidx[b * TOPK + slot] = s; g_tval[b * TOPK + slot] = zv; }
        } else if (v >= vT - dlt) {
            int p = atomicAdd(&s_nb, 1);
            if (p < 128) s_bidx[p] = s;
        }
        zrow[s] = zv;
    }
    __syncthreads();

    const int nb   = min(s_nb, 128);
    int need = TOPK - s_slot;
    if (need < 0) need = 0;
    if (need > nb) need = nb;

    // phase 2: cache exact xsum row
    for (int k = tid; k < KDIM; k += 256) s_x[k] = g_xsum[(size_t)b * KDIM + k];
    __syncthreads();

    // phase 3: exact fp64 pre for each boundary candidate
    for (int c = 0; c < nb; c++) {
        const int s = s_bidx[c];
        double a = 0.0;
        for (int k = tid; k < KDIM; k += 256)
            a += (double)s_x[k] * (double)Wenc[(size_t)k * D_SAE + s];
        s_red[tid] = a;
        __syncthreads();
        for (int st = 128; st > 0; st >>= 1) {
            if (tid < st) s_red[tid] += s_red[tid + st];
            __syncthreads();
        }
        if (tid == 0) s_exact[c] = s_red[0] + (double)benc[s];
        __syncthreads();
    }

    // phase 4: pick top-'need' boundary candidates by exact value
    if (tid == 0) {
        const int base = s_slot;
        for (int r = 0; r < need; r++) {
            int best = -1; double bv = -1e300;
            for (int c = 0; c < nb; c++)
                if (s_exact[c] > bv) { bv = s_exact[c]; best = c; }
            const int s = s_bidx[best];
            const float zv = fmaxf((float)bv, 0.0f);
            g_tidx[b * TOPK + base + r] = s;
            g_tval[b * TOPK + base + r] = zv;
            zrow[s] = zv;
            s_exact[best] = -1e301;
        }
    }
}

// ---------------- kernel 5: sparse decode + x_hat + loss --------------------
__global__ __launch_bounds__(512) void decode_kernel(
    const float* __restrict__ Wdec, const float* __restrict__ bdec,
    const float* __restrict__ x,
    float* __restrict__ xhat, float* __restrict__ loss)
{
    const int b = blockIdx.x;
    const int t = threadIdx.x;

    float acc[9];
#pragma unroll
    for (int i = 0; i < 9; i++) acc[i] = bdec[t + i * 512];

    const int*   idxp = g_tidx + b * TOPK;
    const float* valp = g_tval + b * TOPK;

    for (int k = 0; k < TOPK; k++) {
        const float v = valp[k];
        const float* w = Wdec + (size_t)idxp[k] * TLD;
#pragma unroll
        for (int i = 0; i < 9; i++) acc[i] = fmaf(v, w[t + i * 512], acc[i]);
    }

    const float* xb = x + (size_t)b * TLD;
    float* xh = xhat + (size_t)b * TLD;
    float sse = 0.0f;
#pragma unroll
    for (int i = 0; i < 9; i++) {
        const float d = acc[i] - xb[t + i * 512];
        sse += d * d;
        xh[t + i * 512] = acc[i];
    }

    __shared__ float red[512];
    red[t] = sse;
    __syncthreads();
    for (int st = 256; st > 0; st >>= 1) {
        if (t < st) red[t] += red[t + st];
        __syncthreads();
    }
    if (t == 0)
        atomicAdd(loss, red[0] * (1.0f / (float)(B_SZ * T_SZ * L_SZ)));
}

// ---------------- launch ----------------------------------------------------
extern "C" void kernel_launch(void* const* d_in, const int* in_sizes, int n_in,
                              void* d_out, int out_size)
{
    const float* x    = (const float*)d_in[0];
    const float* Wenc = (const float*)d_in[1];
    const float* benc = (const float*)d_in[2];
    const float* Wdec = (const float*)d_in[3];
    const float* bdec = (const float*)d_in[4];

    float* out  = (float*)d_out;
    float* loss = out;
    float* xhat = out + 1;
    float* z    = out + 1 + (size_t)B_SZ * TLD;

    wsplit_kernel<<<4608, 256>>>(Wenc, loss);
    xsum_split_kernel<<<dim3(KDIM / 32, B_SZ / 32), 256>>>(x);

    cudaFuncSetAttribute(encode_gemm_mma,
                         cudaFuncAttributeMaxDynamicSharedMemorySize, SMEM_BYTES);
    encode_gemm_mma<<<dim3(B_SZ / BM, D_SAE / BN), 256, SMEM_BYTES>>>(benc);

    thresh_kernel<<<B_SZ, 256>>>();
    select_kernel<<<B_SZ, 256>>>(Wenc, benc, z);
    decode_kernel<<<B_SZ, 512>>>(Wdec, bdec, x, xhat, loss);
}

// round 9
// speedup vs baseline: 2.2211x; 1.3614x over previous
#include <cuda_runtime.h>
#include <cuda_bf16.h>
#include <cstdint>

#define B_SZ   4096
#define T_SZ   2
#define L_SZ   3
#define D_IN   768
#define D_SAE  16384
#define TOPK   64
#define KDIM   (L_SZ * D_IN)          // 2304
#define TLD    (T_SZ * L_SZ * D_IN)   // 4608

// ---------------- scratch (static device memory; no runtime alloc) ----------
__device__ float         g_xsum[(size_t)B_SZ * KDIM];    // 37.7 MB exact fold [b][k]
__device__ __nv_bfloat16 g_Ah[(size_t)B_SZ * KDIM];      // 18.9 MB  A hi, [m][k]
__device__ __nv_bfloat16 g_Al[(size_t)B_SZ * KDIM];      // 18.9 MB  A lo, [m][k]
__device__ __nv_bfloat16 g_Bh[(size_t)D_SAE * KDIM];     // 75.5 MB  B hi, [n][k]
__device__ __nv_bfloat16 g_Bl[(size_t)D_SAE * KDIM];     // 75.5 MB  B lo, [n][k]
__device__ float         g_pre[(size_t)B_SZ * D_SAE];    // 268 MB
__device__ int   g_tidx[B_SZ * TOPK];
__device__ float g_tval[B_SZ * TOPK];

// ---------------- helpers ---------------------------------------------------
__device__ __forceinline__ uint32_t smem_u32(const void* p) {
    uint32_t a;
    asm("{ .reg .u64 t; cvta.to.shared.u64 t, %1; cvt.u32.u64 %0, t; }" : "=r"(a) : "l"(p));
    return a;
}
#define CP_ASYNC16(sdst, gsrc) \
    asm volatile("cp.async.cg.shared.global [%0], [%1], 16;" :: "r"(sdst), "l"(gsrc))
#define CP_COMMIT()  asm volatile("cp.async.commit_group;")
#define CP_WAIT1()   asm volatile("cp.async.wait_group 1;")
#define CP_WAIT0()   asm volatile("cp.async.wait_group 0;")

#define MMA_BF16(c, a, b) \
    asm volatile("mma.sync.aligned.m16n8k16.row.col.f32.bf16.bf16.f32 " \
        "{%0,%1,%2,%3},{%4,%5,%6,%7},{%8,%9},{%0,%1,%2,%3};" \
        : "+f"((c)[0]), "+f"((c)[1]), "+f"((c)[2]), "+f"((c)[3]) \
        : "r"((a)[0]), "r"((a)[1]), "r"((a)[2]), "r"((a)[3]), \
          "r"((b)[0]), "r"((b)[1]))

__device__ __forceinline__ void bf16_split(float v, __nv_bfloat16& h, __nv_bfloat16& l) {
    h = __float2bfloat16_rn(v);
    l = __float2bfloat16_rn(v - __bfloat162float(h));
}

// ---------------- kernel 0: W_enc [k][n] f32 -> g_Bh/g_Bl [n][k] bf16 -------
__global__ __launch_bounds__(256) void wsplit_kernel(const float* __restrict__ W,
                                                     float* __restrict__ loss)
{
    __shared__ float tile[32][33];
    const int nb = blockIdx.x * 32;      // 512
    const int kb = blockIdx.y * 32;      // 72
    const int tx = threadIdx.x & 31;
    const int ty = threadIdx.x >> 5;     // 0..7
    if (blockIdx.x == 0 && blockIdx.y == 0 && threadIdx.x == 0) *loss = 0.0f;
#pragma unroll
    for (int j = 0; j < 4; j++) {
        const int ky = ty + j * 8;
        tile[ky][tx] = W[(size_t)(kb + ky) * D_SAE + nb + tx];
    }
    __syncthreads();
    const int rw = threadIdx.x >> 4;     // 0..15
    const int cw = threadIdx.x & 15;     // 0..15 -> k pair
#pragma unroll
    for (int p = 0; p < 2; p++) {
        const int nl = rw + p * 16;
        const float v0 = tile[2 * cw][nl];
        const float v1 = tile[2 * cw + 1][nl];
        __nv_bfloat16 h0, l0, h1, l1;
        bf16_split(v0, h0, l0);
        bf16_split(v1, h1, l1);
        __nv_bfloat162 hh; hh.x = h0; hh.y = h1;
        __nv_bfloat162 ll; ll.x = l0; ll.y = l1;
        const size_t o = (size_t)(nb + nl) * KDIM + kb + 2 * cw;
        *(__nv_bfloat162*)&g_Bh[o] = hh;
        *(__nv_bfloat162*)&g_Bl[o] = ll;
    }
}

// ---------------- kernel 1: fold t -> g_xsum f32 + g_Ah/g_Al bf16 [m][k] ----
__global__ __launch_bounds__(256) void xsum_split_kernel(const float* __restrict__ x)
{
    const int idx = blockIdx.x * 256 + threadIdx.x;   // pairs
    if (idx >= B_SZ * (KDIM / 2)) return;
    const int b  = idx / (KDIM / 2);
    const int rp = idx - b * (KDIM / 2);
    const float* xb = x + (size_t)b * TLD + rp * 2;
    const float2 v0 = *(const float2*)xb;
    const float2 v1 = *(const float2*)(xb + KDIM);
    const float a0 = v0.x + v1.x;
    const float a1 = v0.y + v1.y;
    const size_t o = (size_t)b * KDIM + rp * 2;
    *(float2*)&g_xsum[o] = make_float2(a0, a1);
    __nv_bfloat16 h0, l0, h1, l1;
    bf16_split(a0, h0, l0);
    bf16_split(a1, h1, l1);
    __nv_bfloat162 hh; hh.x = h0; hh.y = h1;
    __nv_bfloat162 ll; ll.x = l0; ll.y = l1;
    *(__nv_bfloat162*)&g_Ah[o] = hh;
    *(__nv_bfloat162*)&g_Al[o] = ll;
}

// ---------------- kernel 2: bf16x3 mma.sync GEMM ----------------------------
// pre(4096x16384) = A @ B + bias;  acc += Ah*Bh + Al*Bh + Ah*Bl
#define BM 128
#define BN 256
#define BK 16
#define NKT (KDIM / BK)                  // 144
#define RPAD 24                          // bf16 row stride (16 data + 8 pad) = 48B
#define AH_OFF 0
#define AL_OFF (BM * RPAD)               // bf16 units: 3072
#define BH_OFF (2 * BM * RPAD)           // 6144
#define BL_OFF (BH_OFF + BN * RPAD)      // 12288
#define STAGE_H (BH_OFF + 2 * BN * RPAD) // 18432 bf16 = 36864 B
#define SMEM_BYTES (2 * STAGE_H * 2)     // 73728 B

__global__ __launch_bounds__(256, 1) void encode_gemm_mma(const float* __restrict__ bias)
{
    extern __shared__ __nv_bfloat16 smB[];
    const uint32_t sb = smem_u32(smB);

    const int tid  = threadIdx.x;
    const int wid  = tid >> 5;
    const int lane = tid & 31;
    const int gid  = lane >> 2;          // 0..7
    const int tg   = lane & 3;           // 0..3
    const int mBase = blockIdx.x * BM;   // x = M so a wave shares B via L2
    const int nBase = blockIdx.y * BN;
    const int wM = (wid & 1) * 64;
    const int wN = (wid >> 1) * 64;

    const int ldr = tid >> 1;            // 0..127
    const int ch  = (tid & 1) * 8;       // bf16 chunk offset

#define ISSUE_STAGE(kt, buf)                                                         \
    do {                                                                             \
        const int _k0 = (kt) * BK;                                                   \
        const uint32_t _sf = sb + (buf) * (STAGE_H * 2);                             \
        CP_ASYNC16(_sf + (AH_OFF + ldr * RPAD + ch) * 2,                             \
                   g_Ah + (size_t)(mBase + ldr) * KDIM + _k0 + ch);                  \
        CP_ASYNC16(_sf + (AL_OFF + ldr * RPAD + ch) * 2,                             \
                   g_Al + (size_t)(mBase + ldr) * KDIM + _k0 + ch);                  \
        _Pragma("unroll")                                                            \
        for (int p = 0; p < 2; p++) {                                                \
            const int r2 = ldr + p * 128;                                            \
            CP_ASYNC16(_sf + (BH_OFF + r2 * RPAD + ch) * 2,                          \
                       g_Bh + (size_t)(nBase + r2) * KDIM + _k0 + ch);               \
            CP_ASYNC16(_sf + (BL_OFF + r2 * RPAD + ch) * 2,                          \
                       g_Bl + (size_t)(nBase + r2) * KDIM + _k0 + ch);               \
        }                                                                            \
    } while (0)

    float acc[4][8][4];
#pragma unroll
    for (int i = 0; i < 4; i++)
#pragma unroll
        for (int j = 0; j < 8; j++)
#pragma unroll
            for (int q = 0; q < 4; q++) acc[i][j][q] = 0.0f;

    ISSUE_STAGE(0, 0);
    CP_COMMIT();

    for (int kt = 0; kt < NKT; ++kt) {
        if (kt + 1 < NKT) {
            ISSUE_STAGE(kt + 1, (kt + 1) & 1);
            CP_COMMIT();
            CP_WAIT1();
        } else {
            CP_WAIT0();
        }
        __syncthreads();

        const __nv_bfloat16* st  = smB + (kt & 1) * STAGE_H;
        const __nv_bfloat16* pAh = st + AH_OFF;
        const __nv_bfloat16* pAl = st + AL_OFF;
        const __nv_bfloat16* pBh = st + BH_OFF;
        const __nv_bfloat16* pBl = st + BL_OFF;

        uint32_t bh[8][2], bl[8][2];
#pragma unroll
        for (int nf = 0; nf < 8; nf++) {
            const int n = wN + nf * 8 + gid;
            const uint32_t o = n * RPAD + tg * 2;
            bh[nf][0] = *(const uint32_t*)(pBh + o);
            bh[nf][1] = *(const uint32_t*)(pBh + o + 8);
            bl[nf][0] = *(const uint32_t*)(pBl + o);
            bl[nf][1] = *(const uint32_t*)(pBl + o + 8);
        }
#pragma unroll
        for (int mf = 0; mf < 4; mf++) {
            const int m = wM + mf * 16 + gid;
            const uint32_t o0 = m * RPAD + tg * 2;
            const uint32_t o1 = (m + 8) * RPAD + tg * 2;
            uint32_t ah[4], al[4];
            ah[0] = *(const uint32_t*)(pAh + o0);
            ah[1] = *(const uint32_t*)(pAh + o1);
            ah[2] = *(const uint32_t*)(pAh + o0 + 8);
            ah[3] = *(const uint32_t*)(pAh + o1 + 8);
            al[0] = *(const uint32_t*)(pAl + o0);
            al[1] = *(const uint32_t*)(pAl + o1);
            al[2] = *(const uint32_t*)(pAl + o0 + 8);
            al[3] = *(const uint32_t*)(pAl + o1 + 8);
#pragma unroll
            for (int nf = 0; nf < 8; nf++) {
                MMA_BF16(acc[mf][nf], ah, bh[nf]);
                MMA_BF16(acc[mf][nf], al, bh[nf]);
                MMA_BF16(acc[mf][nf], ah, bl[nf]);
            }
        }
        __syncthreads();
    }

    // epilogue: +bias, write g_pre
    float2 bv[8];
#pragma unroll
    for (int nf = 0; nf < 8; nf++)
        bv[nf] = *(const float2*)(bias + nBase + wN + nf * 8 + tg * 2);

#pragma unroll
    for (int mf = 0; mf < 4; mf++) {
        const int r0 = mBase + wM + mf * 16 + gid;
#pragma unroll
        for (int nf = 0; nf < 8; nf++) {
            const int col = nBase + wN + nf * 8 + tg * 2;
            float2 v0, v1;
            v0.x = acc[mf][nf][0] + bv[nf].x;
            v0.y = acc[mf][nf][1] + bv[nf].y;
            v1.x = acc[mf][nf][2] + bv[nf].x;
            v1.y = acc[mf][nf][3] + bv[nf].y;
            *(float2*)(g_pre + (size_t)r0 * D_SAE + col)       = v0;
            *(float2*)(g_pre + (size_t)(r0 + 8) * D_SAE + col) = v1;
        }
    }
}

// ---------------- kernel 3: fused topk + select -----------------------------
__device__ __forceinline__ unsigned int fmap(float f)
{
    unsigned int u = __float_as_uint(f);
    return (u & 0x80000000u) ? ~u : (u | 0x80000000u);
}
__device__ __forceinline__ float finv(unsigned int u)
{
    return (u & 0x80000000u) ? __uint_as_float(u ^ 0x80000000u)
                             : __uint_as_float(~u);
}

#define CAP 7168
// smem layout (bytes):
//   s_red    [0,      2048)   double[256]
//   s_exact  [2048,   3072)   double[128]
//   s_x      [3072,  12288)   float[KDIM]
//   cand_u   [12288, 40960)   uint32[CAP]
//   cand_s   [40960, 69632)   int[CAP]
//   hist     [69632, 70656)   int[256]
//   s_bidx   [70656, 71168)   int[128]
#define TKS_SMEM 71168

__global__ __launch_bounds__(256) void topk_select_kernel(
    const float* __restrict__ Wenc, const float* __restrict__ benc,
    float* __restrict__ z)
{
    extern __shared__ char smx[];
    double*   s_red   = (double*)smx;
    double*   s_exact = (double*)(smx + 2048);
    float*    s_x     = (float*)(smx + 3072);
    uint32_t* cand_u  = (uint32_t*)(smx + 12288);
    int*      cand_s  = (int*)(smx + 40960);
    int*      hist    = (int*)(smx + 69632);
    int*      s_bidx  = (int*)(smx + 70656);
    __shared__ int s_nc, s_slot, s_nb, s_bsel, s_need;
    __shared__ unsigned int s_prefix;

    const int b   = blockIdx.x;
    const int tid = threadIdx.x;
    const float* row = g_pre + (size_t)b * D_SAE;
    float* zrow = z + (size_t)b * D_SAE;

    if (tid == 0) { s_nc = 0; s_slot = 0; s_nb = 0; }
    hist[tid] = 0;
    __syncthreads();

    // pass 1: top-byte histogram + zero z; cache exact xsum row
    for (int k = tid; k < KDIM; k += 256) s_x[k] = g_xsum[(size_t)b * KDIM + k];
    for (int s = tid; s < D_SAE; s += 256) {
        const unsigned int u = fmap(row[s]);
        atomicAdd(&hist[u >> 24], 1);
        zrow[s] = 0.0f;
    }
    __syncthreads();
    if (tid == 0) {
        int cum = 0, bsel = 0;
        for (int bb = 255; bb >= 0; --bb) {
            if (cum + hist[bb] >= TOPK) { bsel = bb; break; }
            cum += hist[bb];
        }
        s_bsel = bsel;
    }
    __syncthreads();

    // pass 2: collect candidates with top byte >= bsel.
    // Provably contains the entire top-64 (anything with a smaller top byte is
    // smaller than every top-64 member). E[count] ~ 3.4K << CAP.
    const unsigned int bsel = (unsigned int)s_bsel;
    for (int s = tid; s < D_SAE; s += 256) {
        const unsigned int u = fmap(row[s]);
        if ((u >> 24) >= bsel) {
            const int p = atomicAdd(&s_nc, 1);
            if (p < CAP) { cand_u[p] = u; cand_s[p] = s; }
        }
    }
    __syncthreads();
    const int nc = min(s_nc, CAP);

    // exact radix select of the 64th-largest over candidates (smem only)
    if (tid == 0) { s_prefix = 0u; s_need = TOPK; }
    __syncthreads();
    for (int p = 3; p >= 0; --p) {
        hist[tid] = 0;
        __syncthreads();
        const unsigned int himask = (p == 3) ? 0u : (0xFFFFFFFFu << (8 * (p + 1)));
        const unsigned int prefix = s_prefix;
        for (int c = tid; c < nc; c += 256) {
            const unsigned int u = cand_u[c];
            if ((u & himask) == prefix)
                atomicAdd(&hist[(u >> (8 * p)) & 0xFF], 1);
        }
        __syncthreads();
        if (tid == 0) {
            int need = s_need, cum = 0, bs = 0;
            for (int bb = 255; bb >= 0; --bb) {
                if (cum + hist[bb] >= need) { bs = bb; break; }
                cum += hist[bb];
            }
            s_prefix = prefix | ((unsigned int)bs << (8 * p));
            s_need   = need - cum;
        }
        __syncthreads();
    }

    const float vT  = finv(s_prefix);
    const float dlt = 1e-3f;
    // lowest value mapping into bucket bsel; if vT - dlt dips below it, the
    // candidate list may clip the boundary window -> rare full-row fallback.
    const float v_lo = finv(bsel << 24);
    const bool  full_boundary = (vT - dlt) < v_lo;

    // classify safe-in (always from candidates) + boundary
    for (int c = tid; c < nc; c += 256) {
        const float v = finv(cand_u[c]);
        if (v > vT + dlt) {
            const float zv = fmaxf(v, 0.0f);
            const int slot = atomicAdd(&s_slot, 1);
            g_tidx[b * TOPK + slot] = cand_s[c];
            g_tval[b * TOPK + slot] = zv;
            zrow[cand_s[c]] = zv;
        } else if (!full_boundary && v >= vT - dlt) {
            const int p = atomicAdd(&s_nb, 1);
            if (p < 128) s_bidx[p] = cand_s[c];
        }
    }
    if (full_boundary) {
        __syncthreads();
        for (int s = tid; s < D_SAE; s += 256) {
            const float v = row[s];
            if (v >= vT - dlt && v <= vT + dlt) {
                const int p = atomicAdd(&s_nb, 1);
                if (p < 128) s_bidx[p] = s;
            }
        }
    }
    __syncthreads();
    const int nb = min(s_nb, 128);
    int need = TOPK - s_slot;
    if (need < 0) need = 0;
    if (need > nb) need = nb;

    // exact fp64 pre for boundary candidates
    for (int c = 0; c < nb; c++) {
        const int s = s_bidx[c];
        double a = 0.0;
        for (int k = tid; k < KDIM; k += 256)
            a += (double)s_x[k] * (double)Wenc[(size_t)k * D_SAE + s];
        s_red[tid] = a;
        __syncthreads();
        for (int st = 128; st > 0; st >>= 1) {
            if (tid < st) s_red[tid] += s_red[tid + st];
            __syncthreads();
        }
        if (tid == 0) s_exact[c] = s_red[0] + (double)benc[s];
        __syncthreads();
    }

    if (tid == 0) {
        const int base = s_slot;
        for (int r = 0; r < need; r++) {
            int best = -1; double bv = -1e300;
            for (int c = 0; c < nb; c++)
                if (s_exact[c] > bv) { bv = s_exact[c]; best = c; }
            const int s = s_bidx[best];
            const float zv = fmaxf((float)bv, 0.0f);
            g_tidx[b * TOPK + base + r] = s;
            g_tval[b * TOPK + base + r] = zv;
            zrow[s] = zv;
            s_exact[best] = -1e301;
        }
    }
}

// ---------------- kernel 4: sparse decode + x_hat + loss --------------------
__global__ __launch_bounds__(512) void decode_kernel(
    const float* __restrict__ Wdec, const float* __restrict__ bdec,
    const float* __restrict__ x,
    float* __restrict__ xhat, float* __restrict__ loss)
{
    const int b = blockIdx.x;
    const int t = threadIdx.x;

    float acc[9];
#pragma unroll
    for (int i = 0; i < 9; i++) acc[i] = bdec[t + i * 512];

    const int*   idxp = g_tidx + b * TOPK;
    const float* valp = g_tval + b * TOPK;

    for (int k = 0; k < TOPK; k++) {
        const float v = valp[k];
        const float* w = Wdec + (size_t)idxp[k] * TLD;
#pragma unroll
        for (int i = 0; i < 9; i++) acc[i] = fmaf(v, w[t + i * 512], acc[i]);
    }

    const float* xb = x + (size_t)b * TLD;
    float* xh = xhat + (size_t)b * TLD;
    float sse = 0.0f;
#pragma unroll
    for (int i = 0; i < 9; i++) {
        const float d = acc[i] - xb[t + i * 512];
        sse += d * d;
        xh[t + i * 512] = acc[i];
    }

    __shared__ float red[512];
    red[t] = sse;
    __syncthreads();
    for (int st = 256; st > 0; st >>= 1) {
        if (t < st) red[t] += red[t + st];
        __syncthreads();
    }
    if (t == 0)
        atomicAdd(loss, red[0] * (1.0f / (float)(B_SZ * T_SZ * L_SZ)));
}

// ---------------- launch ----------------------------------------------------
extern "C" void kernel_launch(void* const* d_in, const int* in_sizes, int n_in,
                              void* d_out, int out_size)
{
    const float* x    = (const float*)d_in[0];
    const float* Wenc = (const float*)d_in[1];
    const float* benc = (const float*)d_in[2];
    const float* Wdec = (const float*)d_in[3];
    const float* bdec = (const float*)d_in[4];

    float* out  = (float*)d_out;
    float* loss = out;
    float* xhat = out + 1;
    float* z    = out + 1 + (size_t)B_SZ * TLD;

    // 0) split+transpose W_enc -> Bh/Bl [n][k] bf16 (+ zero loss)
    wsplit_kernel<<<dim3(D_SAE / 32, KDIM / 32), 256>>>(Wenc, loss);
    // 1) fold t -> g_xsum + split Ah/Al [m][k] bf16
    {
        const int n = B_SZ * (KDIM / 2);
        xsum_split_kernel<<<(n + 255) / 256, 256>>>(x);
    }
    // 2) encode GEMM via bf16x3 mma.sync
    cudaFuncSetAttribute(encode_gemm_mma,
                         cudaFuncAttributeMaxDynamicSharedMemorySize, SMEM_BYTES);
    encode_gemm_mma<<<dim3(B_SZ / BM, D_SAE / BN), 256, SMEM_BYTES>>>(benc);
    // 3) fused top-64 + select (exact fp64 boundary re-rank)
    cudaFuncSetAttribute(topk_select_kernel,
                         cudaFuncAttributeMaxDynamicSharedMemorySize, TKS_SMEM);
    topk_select_kernel<<<B_SZ, 256, TKS_SMEM>>>(Wenc, benc, z);
    // 4) sparse decode + loss
    decode_kernel<<<B_SZ, 512>>>(Wdec, bdec, x, xhat, loss);
}

// round 13
// speedup vs baseline: 2.3978x; 1.0796x over previous
#include <cuda_runtime.h>
#include <cuda_bf16.h>
#include <cstdint>
#include <cfloat>

#define B_SZ   4096
#define T_SZ   2
#define L_SZ   3
#define D_IN   768
#define D_SAE  16384
#define TOPK   64
#define KDIM   (L_SZ * D_IN)          // 2304
#define TLD    (T_SZ * L_SZ * D_IN)   // 4608

// ---------------- scratch (static device memory; no runtime alloc) ----------
__device__ float         g_xsum[(size_t)B_SZ * KDIM];    // 37.7 MB exact fold [b][k]
__device__ __nv_bfloat16 g_Ah[(size_t)B_SZ * KDIM];      // A hi, [m][k]
__device__ __nv_bfloat16 g_Al[(size_t)B_SZ * KDIM];      // A lo, [m][k]
__device__ __nv_bfloat16 g_Bh[(size_t)D_SAE * KDIM];     // B hi, [n][k]
__device__ __nv_bfloat16 g_Bl[(size_t)D_SAE * KDIM];     // B lo, [n][k]
__device__ float         g_pre[(size_t)B_SZ * D_SAE];    // 268 MB

// ---------------- helpers ---------------------------------------------------
__device__ __forceinline__ uint32_t smem_u32(const void* p) {
    uint32_t a;
    asm("{ .reg .u64 t; cvta.to.shared.u64 t, %1; cvt.u32.u64 %0, t; }" : "=r"(a) : "l"(p));
    return a;
}
#define CP_ASYNC16(sdst, gsrc) \
    asm volatile("cp.async.cg.shared.global [%0], [%1], 16;" :: "r"(sdst), "l"(gsrc))
#define CP_COMMIT()  asm volatile("cp.async.commit_group;")
#define CP_WAIT1()   asm volatile("cp.async.wait_group 1;")
#define CP_WAIT0()   asm volatile("cp.async.wait_group 0;")

#define LDSM4(r0, r1, r2, r3, addr) \
    asm volatile("ldmatrix.sync.aligned.m8n8.x4.shared.b16 {%0,%1,%2,%3}, [%4];" \
        : "=r"(r0), "=r"(r1), "=r"(r2), "=r"(r3) : "r"(addr))

#define MMA_BF16(c, a0, a1, a2, a3, b0, b1) \
    asm volatile("mma.sync.aligned.m16n8k16.row.col.f32.bf16.bf16.f32 " \
        "{%0,%1,%2,%3},{%4,%5,%6,%7},{%8,%9},{%0,%1,%2,%3};" \
        : "+f"((c)[0]), "+f"((c)[1]), "+f"((c)[2]), "+f"((c)[3]) \
        : "r"(a0), "r"(a1), "r"(a2), "r"(a3), "r"(b0), "r"(b1))

__device__ __forceinline__ void bf16_split(float v, __nv_bfloat16& h, __nv_bfloat16& l) {
    h = __float2bfloat16_rn(v);
    l = __float2bfloat16_rn(v - __bfloat162float(h));
}

// ---------------- kernel 0: W_enc [k][n] f32 -> g_Bh/g_Bl [n][k] bf16 -------
__global__ __launch_bounds__(256) void wsplit_kernel(const float* __restrict__ W,
                                                     float* __restrict__ loss)
{
    __shared__ float tile[32][33];
    const int nb = blockIdx.x * 32;
    const int kb = blockIdx.y * 32;
    const int tx = threadIdx.x & 31;
    const int ty = threadIdx.x >> 5;
    if (blockIdx.x == 0 && blockIdx.y == 0 && threadIdx.x == 0) *loss = 0.0f;
#pragma unroll
    for (int j = 0; j < 4; j++) {
        const int ky = ty + j * 8;
        tile[ky][tx] = W[(size_t)(kb + ky) * D_SAE + nb + tx];
    }
    __syncthreads();
    const int rw = threadIdx.x >> 4;
    const int cw = threadIdx.x & 15;
#pragma unroll
    for (int p = 0; p < 2; p++) {
        const int nl = rw + p * 16;
        const float v0 = tile[2 * cw][nl];
        const float v1 = tile[2 * cw + 1][nl];
        __nv_bfloat16 h0, l0, h1, l1;
        bf16_split(v0, h0, l0);
        bf16_split(v1, h1, l1);
        __nv_bfloat162 hh; hh.x = h0; hh.y = h1;
        __nv_bfloat162 ll; ll.x = l0; ll.y = l1;
        const size_t o = (size_t)(nb + nl) * KDIM + kb + 2 * cw;
        *(__nv_bfloat162*)&g_Bh[o] = hh;
        *(__nv_bfloat162*)&g_Bl[o] = ll;
    }
}

// ---------------- kernel 1: fold t -> g_xsum f32 + g_Ah/g_Al bf16 [m][k] ----
__global__ __launch_bounds__(256) void xsum_split_kernel(const float* __restrict__ x)
{
    const int idx = blockIdx.x * 256 + threadIdx.x;
    if (idx >= B_SZ * (KDIM / 2)) return;
    const int b  = idx / (KDIM / 2);
    const int rp = idx - b * (KDIM / 2);
    const float* xb = x + (size_t)b * TLD + rp * 2;
    const float2 v0 = *(const float2*)xb;
    const float2 v1 = *(const float2*)(xb + KDIM);
    const float a0 = v0.x + v1.x;
    const float a1 = v0.y + v1.y;
    const size_t o = (size_t)b * KDIM + rp * 2;
    *(float2*)&g_xsum[o] = make_float2(a0, a1);
    __nv_bfloat16 h0, l0, h1, l1;
    bf16_split(a0, h0, l0);
    bf16_split(a1, h1, l1);
    __nv_bfloat162 hh; hh.x = h0; hh.y = h1;
    __nv_bfloat162 ll; ll.x = l0; ll.y = l1;
    *(__nv_bfloat162*)&g_Ah[o] = hh;
    *(__nv_bfloat162*)&g_Al[o] = ll;
}

// ---------------- kernel 2: bf16x3 mma.sync GEMM (ldmatrix fragments) -------
#define BM 128
#define BN 256
#define BK 16
#define NKT (KDIM / BK)                  // 144
#define RPAD 24                          // bf16 row stride = 48B (conflict-free LDSM)
#define AH_OFF 0
#define AL_OFF (BM * RPAD)
#define BH_OFF (2 * BM * RPAD)
#define BL_OFF (BH_OFF + BN * RPAD)
#define STAGE_H (BH_OFF + 2 * BN * RPAD) // 18432 bf16 = 36864 B
#define SMEM_BYTES (2 * STAGE_H * 2)     // 73728 B

__global__ __launch_bounds__(256, 1) void encode_gemm_mma(const float* __restrict__ bias)
{
    extern __shared__ __nv_bfloat16 smB[];
    const uint32_t sb = smem_u32(smB);

    const int tid  = threadIdx.x;
    const int wid  = tid >> 5;
    const int lane = tid & 31;
    const int gid  = lane >> 2;
    const int tg   = lane & 3;
    const int mBase = blockIdx.x * BM;
    const int nBase = blockIdx.y * BN;
    const int wM = (wid & 1) * 64;
    const int wN = (wid >> 1) * 64;

    const int ldr = tid >> 1;
    const int ch  = (tid & 1) * 8;

    // LDSM lane address components (bytes within stage)
    const uint32_t aOff = (uint32_t)((AH_OFF + (wM + (lane & 15)) * RPAD) * 2 + (lane >> 4) * 16);
    const uint32_t bOff = (uint32_t)((BH_OFF + (wN + (lane & 7) + ((lane >> 4) & 1) * 8) * RPAD) * 2
                                     + ((lane >> 3) & 1) * 16);

#define ISSUE_STAGE(kt, buf)                                                         \
    do {                                                                             \
        const int _k0 = (kt) * BK;                                                   \
        const uint32_t _sf = sb + (buf) * (STAGE_H * 2);                             \
        CP_ASYNC16(_sf + (AH_OFF + ldr * RPAD + ch) * 2,                             \
                   g_Ah + (size_t)(mBase + ldr) * KDIM + _k0 + ch);                  \
        CP_ASYNC16(_sf + (AL_OFF + ldr * RPAD + ch) * 2,                             \
                   g_Al + (size_t)(mBase + ldr) * KDIM + _k0 + ch);                  \
        _Pragma("unroll")                                                            \
        for (int p = 0; p < 2; p++) {                                                \
            const int r2 = ldr + p * 128;                                            \
            CP_ASYNC16(_sf + (BH_OFF + r2 * RPAD + ch) * 2,                          \
                       g_Bh + (size_t)(nBase + r2) * KDIM + _k0 + ch);               \
            CP_ASYNC16(_sf + (BL_OFF + r2 * RPAD + ch) * 2,                          \
                       g_Bl + (size_t)(nBase + r2) * KDIM + _k0 + ch);               \
        }                                                                            \
    } while (0)

    float acc[4][8][4];
#pragma unroll
    for (int i = 0; i < 4; i++)
#pragma unroll
        for (int j = 0; j < 8; j++)
#pragma unroll
            for (int q = 0; q < 4; q++) acc[i][j][q] = 0.0f;

    ISSUE_STAGE(0, 0);
    CP_COMMIT();

    for (int kt = 0; kt < NKT; ++kt) {
        if (kt + 1 < NKT) {
            ISSUE_STAGE(kt + 1, (kt + 1) & 1);
            CP_COMMIT();
            CP_WAIT1();
        } else {
            CP_WAIT0();
        }
        __syncthreads();

        const uint32_t stg = sb + (kt & 1) * (STAGE_H * 2);
        const uint32_t aAddr = stg + aOff;
        const uint32_t bAddr = stg + bOff;

        uint32_t ah[4][4], al[4][4], bh[4][4], bl[4][4];
#pragma unroll
        for (int mf = 0; mf < 4; mf++) {
            LDSM4(ah[mf][0], ah[mf][1], ah[mf][2], ah[mf][3], aAddr + mf * (16 * RPAD * 2));
            LDSM4(al[mf][0], al[mf][1], al[mf][2], al[mf][3],
                  aAddr + mf * (16 * RPAD * 2) + (AL_OFF - AH_OFF) * 2);
        }
#pragma unroll
        for (int p = 0; p < 4; p++) {
            LDSM4(bh[p][0], bh[p][1], bh[p][2], bh[p][3], bAddr + p * (16 * RPAD * 2));
            LDSM4(bl[p][0], bl[p][1], bl[p][2], bl[p][3],
                  bAddr + p * (16 * RPAD * 2) + (BL_OFF - BH_OFF) * 2);
        }

#pragma unroll
        for (int mf = 0; mf < 4; mf++) {
#pragma unroll
            for (int nf = 0; nf < 8; nf++) {
                const int hp = nf >> 1, hq = (nf & 1) * 2;
                MMA_BF16(acc[mf][nf], ah[mf][0], ah[mf][1], ah[mf][2], ah[mf][3],
                         bh[hp][hq], bh[hp][hq + 1]);
                MMA_BF16(acc[mf][nf], al[mf][0], al[mf][1], al[mf][2], al[mf][3],
                         bh[hp][hq], bh[hp][hq + 1]);
                MMA_BF16(acc[mf][nf], ah[mf][0], ah[mf][1], ah[mf][2], ah[mf][3],
                         bl[hp][hq], bl[hp][hq + 1]);
            }
        }
        __syncthreads();
    }

    float2 bv[8];
#pragma unroll
    for (int nf = 0; nf < 8; nf++)
        bv[nf] = *(const float2*)(bias + nBase + wN + nf * 8 + tg * 2);

#pragma unroll
    for (int mf = 0; mf < 4; mf++) {
        const int r0 = mBase + wM + mf * 16 + gid;
#pragma unroll
        for (int nf = 0; nf < 8; nf++) {
            const int col = nBase + wN + nf * 8 + tg * 2;
            float2 v0, v1;
            v0.x = acc[mf][nf][0] + bv[nf].x;
            v0.y = acc[mf][nf][1] + bv[nf].y;
            v1.x = acc[mf][nf][2] + bv[nf].x;
            v1.y = acc[mf][nf][3] + bv[nf].y;
            *(float2*)(g_pre + (size_t)r0 * D_SAE + col)       = v0;
            *(float2*)(g_pre + (size_t)(r0 + 8) * D_SAE + col) = v1;
        }
    }
}

// ---------------- kernel 3: fused topk + select + decode --------------------
__device__ __forceinline__ unsigned int fmap(float f)
{
    unsigned int u = __float_as_uint(f);
    return (u & 0x80000000u) ? ~u : (u | 0x80000000u);
}
__device__ __forceinline__ float finv(unsigned int u)
{
    return (u & 0x80000000u) ? __uint_as_float(u ^ 0x80000000u)
                             : __uint_as_float(~u);
}

#define CAP 4096
#define NTH 512
// dynamic smem layout (bytes):
//   s_red    [0,     4096)   double[512]  (aliased as float scratch in decode)
//   s_exact  [4096,  5120)   double[128]
//   s_x      [5120, 14336)   float[KDIM]
//   cand_u   [14336, 30720)  uint32[CAP]
//   cand_s   [30720, 38912)  uint16[CAP]
//   hist     [38912, 39936)  int[256]
//   s_bidx   [39936, 40448)  int[128]
//   s_tidx   [40448, 40704)  int[64]
//   s_tval   [40704, 40960)  float[64]
#define TKD_SMEM 40960

__global__ __launch_bounds__(NTH) void topk_decode_kernel(
    const float* __restrict__ Wenc, const float* __restrict__ benc,
    const float* __restrict__ Wdec, const float* __restrict__ bdec,
    const float* __restrict__ x,
    float* __restrict__ z, float* __restrict__ xhat, float* __restrict__ loss)
{
    extern __shared__ char smx[];
    double*   s_red   = (double*)smx;
    double*   s_exact = (double*)(smx + 4096);
    float*    s_x     = (float*)(smx + 5120);
    uint32_t* cand_u  = (uint32_t*)(smx + 14336);
    uint16_t* cand_s  = (uint16_t*)(smx + 30720);
    int*      hist    = (int*)(smx + 38912);
    int*      s_bidx  = (int*)(smx + 39936);
    int*      s_tidx  = (int*)(smx + 40448);
    float*    s_tval  = (float*)(smx + 40704);
    __shared__ int s_nc, s_slot, s_nb, s_need;
    __shared__ unsigned int s_prefix;
    __shared__ float s_t;

    const int b    = blockIdx.x;
    const int tid  = threadIdx.x;
    const int lane = tid & 31;
    const float* row = g_pre + (size_t)b * D_SAE;
    float* zrow = z + (size_t)b * D_SAE;   // NOTE: only 4-byte aligned (z = out+1+...)

    if (tid == 0) { s_nc = 0; s_slot = 0; s_nb = 0; s_t = 4.0f; }
    __syncthreads();

    // load exact xsum row
    for (int k = tid; k < KDIM; k += NTH) s_x[k] = g_xsum[(size_t)b * KDIM + k];

    // pass 1: zero z (SCALAR stores — z is misaligned for vector access) +
    // collect candidates v > t (warp-aggregated push). Exact bisection retry
    // if the count leaves [TOPK, CAP]; fast path = single pass.
    float t_lo = -FLT_MAX, t_hi = FLT_MAX;
    for (int attempt = 0; attempt < 64; ++attempt) {
        const float t = s_t;
        const bool first = (attempt == 0);
        const float4* row4 = (const float4*)row;   // g_pre is 16B-aligned
        for (int j = tid; j < D_SAE / 4; j += NTH) {
            const float4 v = row4[j];
            if (first) {
                zrow[4 * j + 0] = 0.0f;
                zrow[4 * j + 1] = 0.0f;
                zrow[4 * j + 2] = 0.0f;
                zrow[4 * j + 3] = 0.0f;
            }
#pragma unroll
            for (int q = 0; q < 4; q++) {
                const float vv = (q == 0) ? v.x : (q == 1) ? v.y : (q == 2) ? v.z : v.w;
                const bool pr = vv > t;
                const unsigned m = __ballot_sync(0xFFFFFFFFu, pr);
                if (m) {
                    const int ldm = __ffs(m) - 1;
                    int base = 0;
                    if (lane == ldm) base = atomicAdd(&s_nc, __popc(m));
                    base = __shfl_sync(0xFFFFFFFFu, base, ldm);
                    if (pr) {
                        const int off = base + __popc(m & ((1u << lane) - 1u));
                        if (off < CAP) {
                            cand_u[off] = fmap(vv);
                            cand_s[off] = (uint16_t)(4 * j + q);
                        }
                    }
                }
            }
        }
        __syncthreads();
        const int nc_try = s_nc;
        if (nc_try >= TOPK && nc_try <= CAP) break;
        if (tid == 0) {
            if (nc_try > CAP) { t_lo = t; s_t = (t_hi == FLT_MAX) ? t + 2.0f : 0.5f * (t + t_hi); }
            else              { t_hi = t; s_t = (t_lo == -FLT_MAX) ? t - 2.0f : 0.5f * (t + t_lo); }
            s_nc = 0;
        }
        __syncthreads();
    }
    const int nc = min(s_nc, CAP);
    const float t_used = s_t;

    // exact radix select of the 64th-largest over candidates
    if (tid == 0) { s_prefix = 0u; s_need = TOPK; }
    __syncthreads();
    for (int p = 3; p >= 0; --p) {
        for (int i = tid; i < 256; i += NTH) hist[i] = 0;
        __syncthreads();
        const unsigned int himask = (p == 3) ? 0u : (0xFFFFFFFFu << (8 * (p + 1)));
        const unsigned int prefix = s_prefix;
        for (int c = tid; c < nc; c += NTH) {
            const unsigned int u = cand_u[c];
            if ((u & himask) == prefix)
                atomicAdd(&hist[(u >> (8 * p)) & 0xFF], 1);
        }
        __syncthreads();
        if (tid == 0) {
            int need = s_need, cum = 0, bs = 0;
            for (int bb = 255; bb >= 0; --bb) {
                if (cum + hist[bb] >= need) { bs = bb; break; }
                cum += hist[bb];
            }
            s_prefix = prefix | ((unsigned int)bs << (8 * p));
            s_need   = need - cum;
        }
        __syncthreads();
    }

    const float vT  = finv(s_prefix);
    const float dlt = 1e-3f;
    const bool  full_boundary = (vT - dlt) <= t_used;   // window clipped -> rare fallback

    // classify: safe-in vs boundary
    for (int c = tid; c < nc; c += NTH) {
        const float v = finv(cand_u[c]);
        if (v > vT + dlt) {
            const int slot = atomicAdd(&s_slot, 1);
            if (slot < TOPK) {
                const float zv = fmaxf(v, 0.0f);
                s_tidx[slot] = cand_s[c];
                s_tval[slot] = zv;
                zrow[cand_s[c]] = zv;
            }
        } else if (!full_boundary && v >= vT - dlt) {
            const int p = atomicAdd(&s_nb, 1);
            if (p < 128) s_bidx[p] = cand_s[c];
        }
    }
    if (full_boundary) {
        __syncthreads();
        for (int s = tid; s < D_SAE; s += NTH) {
            const float v = row[s];
            if (v >= vT - dlt && v <= vT + dlt) {
                const int p = atomicAdd(&s_nb, 1);
                if (p < 128) s_bidx[p] = s;
            }
        }
    }
    __syncthreads();
    const int nb = min(s_nb, 128);
    int need = TOPK - s_slot;
    if (need < 0) need = 0;
    if (need > nb) need = nb;

    // exact fp64 pre for boundary candidates
    for (int c = 0; c < nb; c++) {
        const int s = s_bidx[c];
        double a = 0.0;
        for (int k = tid; k < KDIM; k += NTH)
            a += (double)s_x[k] * (double)Wenc[(size_t)k * D_SAE + s];
        s_red[tid] = a;
        __syncthreads();
        for (int st = NTH / 2; st > 0; st >>= 1) {
            if (tid < st) s_red[tid] += s_red[tid + st];
            __syncthreads();
        }
        if (tid == 0) s_exact[c] = s_red[0] + (double)benc[s];
        __syncthreads();
    }

    if (tid == 0) {
        const int base = s_slot;
        for (int r = 0; r < need; r++) {
            int best = -1; double bv = -1e300;
            for (int c = 0; c < nb; c++)
                if (s_exact[c] > bv) { bv = s_exact[c]; best = c; }
            const int s = s_bidx[best];
            const float zv = fmaxf((float)bv, 0.0f);
            s_tidx[base + r] = s;
            s_tval[base + r] = zv;
            zrow[s] = zv;
            s_exact[best] = -1e301;
        }
    }
    __syncthreads();

    // ---- decode: x_hat = sum_k z_k * Wdec[idx_k] + bdec; fused SSE/loss ----
    float acc[9];
#pragma unroll
    for (int i = 0; i < 9; i++) acc[i] = bdec[tid + i * NTH];

    for (int k = 0; k < TOPK; k++) {
        const float v = s_tval[k];
        const float* w = Wdec + (size_t)s_tidx[k] * TLD;
#pragma unroll
        for (int i = 0; i < 9; i++) acc[i] = fmaf(v, w[tid + i * NTH], acc[i]);
    }

    const float* xb = x + (size_t)b * TLD;
    float* xh = xhat + (size_t)b * TLD;     // 4-byte aligned (out+1) — scalar only
    float sse = 0.0f;
#pragma unroll
    for (int i = 0; i < 9; i++) {
        const float d = acc[i] - xb[tid + i * NTH];
        sse += d * d;
        xh[tid + i * NTH] = acc[i];
    }

    float* f_red = (float*)s_red;
    f_red[tid] = sse;
    __syncthreads();
    for (int st = NTH / 2; st > 0; st >>= 1) {
        if (tid < st) f_red[tid] += f_red[tid + st];
        __syncthreads();
    }
    if (tid == 0)
        atomicAdd(loss, f_red[0] * (1.0f / (float)(B_SZ * T_SZ * L_SZ)));
}

// ---------------- launch ----------------------------------------------------
extern "C" void kernel_launch(void* const* d_in, const int* in_sizes, int n_in,
                              void* d_out, int out_size)
{
    const float* x    = (const float*)d_in[0];
    const float* Wenc = (const float*)d_in[1];
    const float* benc = (const float*)d_in[2];
    const float* Wdec = (const float*)d_in[3];
    const float* bdec = (const float*)d_in[4];

    float* out  = (float*)d_out;
    float* loss = out;
    float* xhat = out + 1;
    float* z    = out + 1 + (size_t)B_SZ * TLD;

    // 0) split+transpose W_enc -> Bh/Bl [n][k] bf16 (+ zero loss)
    wsplit_kernel<<<dim3(D_SAE / 32, KDIM / 32), 256>>>(Wenc, loss);
    // 1) fold t -> g_xsum + split Ah/Al [m][k] bf16
    {
        const int n = B_SZ * (KDIM / 2);
        xsum_split_kernel<<<(n + 255) / 256, 256>>>(x);
    }
    // 2) encode GEMM via bf16x3 mma.sync + ldmatrix
    cudaFuncSetAttribute(encode_gemm_mma,
                         cudaFuncAttributeMaxDynamicSharedMemorySize, SMEM_BYTES);
    encode_gemm_mma<<<dim3(B_SZ / BM, D_SAE / BN), 256, SMEM_BYTES>>>(benc);
    // 3) fused top-64 select (exact) + sparse decode + loss
    cudaFuncSetAttribute(topk_decode_kernel,
                         cudaFuncAttributeMaxDynamicSharedMemorySize, TKD_SMEM);
    topk_decode_kernel<<<B_SZ, NTH, TKD_SMEM>>>(Wenc, benc, Wdec, bdec, x, z, xhat, loss);
}

// round 14
// speedup vs baseline: 4.3051x; 1.7955x over previous
#include <cuda_runtime.h>
#include <cuda_fp16.h>
#include <cstdint>
#include <cfloat>

#define B_SZ   4096
#define T_SZ   2
#define L_SZ   3
#define D_IN   768
#define D_SAE  16384
#define TOPK   64
#define KDIM   (L_SZ * D_IN)          // 2304
#define TLD    (T_SZ * L_SZ * D_IN)   // 4608

// ---------------- scratch (static device memory; no runtime alloc) ----------
__device__ float  g_xsum[(size_t)B_SZ * KDIM];    // exact fold [b][k]
__device__ __half g_Af[(size_t)B_SZ * KDIM];      // A fp16, [m][k]
__device__ __half g_Bf[(size_t)D_SAE * KDIM];     // B fp16, [n][k]
__device__ float  g_WT[(size_t)D_SAE * KDIM];     // W_enc^T fp32 [n][k] (exact, for re-rank)
__device__ __half g_Wd[(size_t)D_SAE * TLD];      // W_dec fp16
__device__ float  g_pre[(size_t)B_SZ * D_SAE];    // 268 MB

// ---------------- helpers ---------------------------------------------------
__device__ __forceinline__ uint32_t smem_u32(const void* p) {
    uint32_t a;
    asm("{ .reg .u64 t; cvta.to.shared.u64 t, %1; cvt.u32.u64 %0, t; }" : "=r"(a) : "l"(p));
    return a;
}
#define CP_ASYNC16(sdst, gsrc) \
    asm volatile("cp.async.cg.shared.global [%0], [%1], 16;" :: "r"(sdst), "l"(gsrc))
#define CP_COMMIT()  asm volatile("cp.async.commit_group;")
#define CP_WAIT1()   asm volatile("cp.async.wait_group 1;")
#define CP_WAIT0()   asm volatile("cp.async.wait_group 0;")

#define LDSM4(r0, r1, r2, r3, addr) \
    asm volatile("ldmatrix.sync.aligned.m8n8.x4.shared.b16 {%0,%1,%2,%3}, [%4];" \
        : "=r"(r0), "=r"(r1), "=r"(r2), "=r"(r3) : "r"(addr))

#define MMA_FP16(c, a0, a1, a2, a3, b0, b1) \
    asm volatile("mma.sync.aligned.m16n8k16.row.col.f32.f16.f16.f32 " \
        "{%0,%1,%2,%3},{%4,%5,%6,%7},{%8,%9},{%0,%1,%2,%3};" \
        : "+f"((c)[0]), "+f"((c)[1]), "+f"((c)[2]), "+f"((c)[3]) \
        : "r"(a0), "r"(a1), "r"(a2), "r"(a3), "r"(b0), "r"(b1))

// ---------------- kernel 0: W_enc [k][n] -> g_Bf fp16 [n][k] + g_WT f32 -----
__global__ __launch_bounds__(256) void wsplit_kernel(const float* __restrict__ W,
                                                     float* __restrict__ loss)
{
    __shared__ float tile[32][33];
    const int nb = blockIdx.x * 32;
    const int kb = blockIdx.y * 32;
    const int tx = threadIdx.x & 31;
    const int ty = threadIdx.x >> 5;
    if (blockIdx.x == 0 && blockIdx.y == 0 && threadIdx.x == 0) *loss = 0.0f;
#pragma unroll
    for (int j = 0; j < 4; j++) {
        const int ky = ty + j * 8;
        tile[ky][tx] = W[(size_t)(kb + ky) * D_SAE + nb + tx];
    }
    __syncthreads();
    const int rw = threadIdx.x >> 4;     // 0..15 (n within tile)
    const int cw = threadIdx.x & 15;     // 0..15 (k pair)
#pragma unroll
    for (int p = 0; p < 2; p++) {
        const int nl = rw + p * 16;
        const float v0 = tile[2 * cw][nl];
        const float v1 = tile[2 * cw + 1][nl];
        const size_t o = (size_t)(nb + nl) * KDIM + kb + 2 * cw;
        __half2 hv; hv.x = __float2half_rn(v0); hv.y = __float2half_rn(v1);
        *(__half2*)&g_Bf[o] = hv;
        *(float2*)&g_WT[o]  = make_float2(v0, v1);
    }
}

// ---------------- kernel 0b: W_dec f32 -> g_Wd fp16 -------------------------
__global__ __launch_bounds__(256) void wdec_kernel(const float* __restrict__ Wd)
{
    const size_t i = ((size_t)blockIdx.x * 256 + threadIdx.x);
    const float4 v = ((const float4*)Wd)[i];
    __half2 h01, h23;
    h01.x = __float2half_rn(v.x); h01.y = __float2half_rn(v.y);
    h23.x = __float2half_rn(v.z); h23.y = __float2half_rn(v.w);
    *(__half2*)&g_Wd[4 * i]     = h01;
    *(__half2*)&g_Wd[4 * i + 2] = h23;
}

// ---------------- kernel 1: fold t -> g_xsum f32 + g_Af fp16 [m][k] ---------
__global__ __launch_bounds__(256) void xsum_split_kernel(const float* __restrict__ x)
{
    const int idx = blockIdx.x * 256 + threadIdx.x;   // pairs
    if (idx >= B_SZ * (KDIM / 2)) return;
    const int b  = idx / (KDIM / 2);
    const int rp = idx - b * (KDIM / 2);
    const float* xb = x + (size_t)b * TLD + rp * 2;
    const float2 v0 = *(const float2*)xb;
    const float2 v1 = *(const float2*)(xb + KDIM);
    const float a0 = v0.x + v1.x;
    const float a1 = v0.y + v1.y;
    const size_t o = (size_t)b * KDIM + rp * 2;
    *(float2*)&g_xsum[o] = make_float2(a0, a1);
    __half2 hv; hv.x = __float2half_rn(a0); hv.y = __float2half_rn(a1);
    *(__half2*)&g_Af[o] = hv;
}

// ---------------- kernel 2: fp16 single-pass mma.sync GEMM ------------------
#define BM 128
#define BN 256
#define BK 16
#define NKT (KDIM / BK)                  // 144
#define RPAD 24                          // 48B row stride, conflict-free LDSM
#define A_OFF 0
#define B_OFF (BM * RPAD)                // 3072 units
#define STAGE_H ((BM + BN) * RPAD)       // 9216 units = 18432 B
#define SMEM_BYTES (2 * STAGE_H * 2)     // 36864 B

__global__ __launch_bounds__(256, 1) void encode_gemm_mma(const float* __restrict__ bias)
{
    extern __shared__ __half smH[];
    const uint32_t sb = smem_u32(smH);

    const int tid  = threadIdx.x;
    const int wid  = tid >> 5;
    const int lane = tid & 31;
    const int gid  = lane >> 2;
    const int tg   = lane & 3;
    const int mBase = blockIdx.x * BM;
    const int nBase = blockIdx.y * BN;
    const int wM = (wid & 1) * 64;
    const int wN = (wid >> 1) * 64;

    const int ldr = tid >> 1;
    const int ch  = (tid & 1) * 8;

    const uint32_t aOff = (uint32_t)((A_OFF + (wM + (lane & 15)) * RPAD) * 2 + (lane >> 4) * 16);
    const uint32_t bOff = (uint32_t)((B_OFF + (wN + (lane & 7) + ((lane >> 4) & 1) * 8) * RPAD) * 2
                                     + ((lane >> 3) & 1) * 16);

#define ISSUE_STAGE(kt, buf)                                                         \
    do {                                                                             \
        const int _k0 = (kt) * BK;                                                   \
        const uint32_t _sf = sb + (buf) * (STAGE_H * 2);                             \
        CP_ASYNC16(_sf + (A_OFF + ldr * RPAD + ch) * 2,                              \
                   g_Af + (size_t)(mBase + ldr) * KDIM + _k0 + ch);                  \
        _Pragma("unroll")                                                            \
        for (int p = 0; p < 2; p++) {                                                \
            const int r2 = ldr + p * 128;                                            \
            CP_ASYNC16(_sf + (B_OFF + r2 * RPAD + ch) * 2,                           \
                       g_Bf + (size_t)(nBase + r2) * KDIM + _k0 + ch);               \
        }                                                                            \
    } while (0)

    float acc[4][8][4];
#pragma unroll
    for (int i = 0; i < 4; i++)
#pragma unroll
        for (int j = 0; j < 8; j++)
#pragma unroll
            for (int q = 0; q < 4; q++) acc[i][j][q] = 0.0f;

    ISSUE_STAGE(0, 0);
    CP_COMMIT();

    for (int kt = 0; kt < NKT; ++kt) {
        if (kt + 1 < NKT) {
            ISSUE_STAGE(kt + 1, (kt + 1) & 1);
            CP_COMMIT();
            CP_WAIT1();
        } else {
            CP_WAIT0();
        }
        __syncthreads();

        const uint32_t stg = sb + (kt & 1) * (STAGE_H * 2);
        const uint32_t aAddr = stg + aOff;
        const uint32_t bAddr = stg + bOff;

        uint32_t af[4][4], bf[4][4];
#pragma unroll
        for (int mf = 0; mf < 4; mf++)
            LDSM4(af[mf][0], af[mf][1], af[mf][2], af[mf][3], aAddr + mf * (16 * RPAD * 2));
#pragma unroll
        for (int p = 0; p < 4; p++)
            LDSM4(bf[p][0], bf[p][1], bf[p][2], bf[p][3], bAddr + p * (16 * RPAD * 2));

#pragma unroll
        for (int mf = 0; mf < 4; mf++) {
#pragma unroll
            for (int nf = 0; nf < 8; nf++) {
                const int hp = nf >> 1, hq = (nf & 1) * 2;
                MMA_FP16(acc[mf][nf], af[mf][0], af[mf][1], af[mf][2], af[mf][3],
                         bf[hp][hq], bf[hp][hq + 1]);
            }
        }
        __syncthreads();
    }

    float2 bv[8];
#pragma unroll
    for (int nf = 0; nf < 8; nf++)
        bv[nf] = *(const float2*)(bias + nBase + wN + nf * 8 + tg * 2);

#pragma unroll
    for (int mf = 0; mf < 4; mf++) {
        const int r0 = mBase + wM + mf * 16 + gid;
#pragma unroll
        for (int nf = 0; nf < 8; nf++) {
            const int col = nBase + wN + nf * 8 + tg * 2;
            float2 v0, v1;
            v0.x = acc[mf][nf][0] + bv[nf].x;
            v0.y = acc[mf][nf][1] + bv[nf].y;
            v1.x = acc[mf][nf][2] + bv[nf].x;
            v1.y = acc[mf][nf][3] + bv[nf].y;
            *(float2*)(g_pre + (size_t)r0 * D_SAE + col)       = v0;
            *(float2*)(g_pre + (size_t)(r0 + 8) * D_SAE + col) = v1;
        }
    }
}

// ---------------- kernel 3: fused topk + select + decode --------------------
__device__ __forceinline__ unsigned int fmap(float f)
{
    unsigned int u = __float_as_uint(f);
    return (u & 0x80000000u) ? ~u : (u | 0x80000000u);
}
__device__ __forceinline__ float finv(unsigned int u)
{
    return (u & 0x80000000u) ? __uint_as_float(u ^ 0x80000000u)
                             : __uint_as_float(~u);
}

#define CAP 4096
#define NTH 512
// dynamic smem layout (bytes):
//   s_red    [0,     4096)   double[512]  (aliased as float scratch in decode)
//   s_exact  [4096,  5120)   double[128]
//   s_x      [5120, 14336)   float[KDIM]
//   cand_u   [14336, 30720)  uint32[CAP]
//   cand_s   [30720, 38912)  uint16[CAP]
//   hist     [38912, 39936)  int[256]
//   s_bidx   [39936, 40448)  int[128]
//   s_tidx   [40448, 40704)  int[64]
//   s_tval   [40704, 40960)  float[64]
#define TKD_SMEM 40960

__global__ __launch_bounds__(NTH) void topk_decode_kernel(
    const float* __restrict__ benc,
    const float* __restrict__ bdec,
    const float* __restrict__ x,
    float* __restrict__ z, float* __restrict__ xhat, float* __restrict__ loss)
{
    extern __shared__ char smx[];
    double*   s_red   = (double*)smx;
    double*   s_exact = (double*)(smx + 4096);
    float*    s_x     = (float*)(smx + 5120);
    uint32_t* cand_u  = (uint32_t*)(smx + 14336);
    uint16_t* cand_s  = (uint16_t*)(smx + 30720);
    int*      hist    = (int*)(smx + 38912);
    int*      s_bidx  = (int*)(smx + 39936);
    int*      s_tidx  = (int*)(smx + 40448);
    float*    s_tval  = (float*)(smx + 40704);
    __shared__ int s_nc, s_slot, s_nb, s_need;
    __shared__ unsigned int s_prefix;
    __shared__ float s_t;

    const int b    = blockIdx.x;
    const int tid  = threadIdx.x;
    const int lane = tid & 31;
    const float* row = g_pre + (size_t)b * D_SAE;
    float* zrow = z + (size_t)b * D_SAE;   // only 4-byte aligned (z = out+1+...)

    if (tid == 0) { s_nc = 0; s_slot = 0; s_nb = 0; s_t = 4.0f; }
    __syncthreads();

    for (int k = tid; k < KDIM; k += NTH) s_x[k] = g_xsum[(size_t)b * KDIM + k];

    // pass 1: zero z (scalar stores) + collect candidates v > t.
    float t_lo = -FLT_MAX, t_hi = FLT_MAX;
    for (int attempt = 0; attempt < 64; ++attempt) {
        const float t = s_t;
        const bool first = (attempt == 0);
        const float4* row4 = (const float4*)row;
        for (int j = tid; j < D_SAE / 4; j += NTH) {
            const float4 v = row4[j];
            if (first) {
                zrow[4 * j + 0] = 0.0f;
                zrow[4 * j + 1] = 0.0f;
                zrow[4 * j + 2] = 0.0f;
                zrow[4 * j + 3] = 0.0f;
            }
#pragma unroll
            for (int q = 0; q < 4; q++) {
                const float vv = (q == 0) ? v.x : (q == 1) ? v.y : (q == 2) ? v.z : v.w;
                const bool pr = vv > t;
                const unsigned m = __ballot_sync(0xFFFFFFFFu, pr);
                if (m) {
                    const int ldm = __ffs(m) - 1;
                    int base = 0;
                    if (lane == ldm) base = atomicAdd(&s_nc, __popc(m));
                    base = __shfl_sync(0xFFFFFFFFu, base, ldm);
                    if (pr) {
                        const int off = base + __popc(m & ((1u << lane) - 1u));
                        if (off < CAP) {
                            cand_u[off] = fmap(vv);
                            cand_s[off] = (uint16_t)(4 * j + q);
                        }
                    }
                }
            }
        }
        __syncthreads();
        const int nc_try = s_nc;
        if (nc_try >= TOPK && nc_try <= CAP) break;
        if (tid == 0) {
            if (nc_try > CAP) { t_lo = t; s_t = (t_hi == FLT_MAX) ? t + 2.0f : 0.5f * (t + t_hi); }
            else              { t_hi = t; s_t = (t_lo == -FLT_MAX) ? t - 2.0f : 0.5f * (t + t_lo); }
            s_nc = 0;
        }
        __syncthreads();
    }
    const int nc = min(s_nc, CAP);
    const float t_used = s_t;

    // exact radix select of the 64th-largest over candidates
    if (tid == 0) { s_prefix = 0u; s_need = TOPK; }
    __syncthreads();
    for (int p = 3; p >= 0; --p) {
        for (int i = tid; i < 256; i += NTH) hist[i] = 0;
        __syncthreads();
        const unsigned int himask = (p == 3) ? 0u : (0xFFFFFFFFu << (8 * (p + 1)));
        const unsigned int prefix = s_prefix;
        for (int c = tid; c < nc; c += NTH) {
            const unsigned int u = cand_u[c];
            if ((u & himask) == prefix)
                atomicAdd(&hist[(u >> (8 * p)) & 0xFF], 1);
        }
        __syncthreads();
        if (tid == 0) {
            int need = s_need, cum = 0, bs = 0;
            for (int bb = 255; bb >= 0; --bb) {
                if (cum + hist[bb] >= need) { bs = bb; break; }
                cum += hist[bb];
            }
            s_prefix = prefix | ((unsigned int)bs << (8 * p));
            s_need   = need - cum;
        }
        __syncthreads();
    }

    const float vT  = finv(s_prefix);
    const float dlt = 1e-2f;            // 20 sigma of fp16 GEMM noise
    const bool  full_boundary = (vT - dlt) <= t_used;

    // classify: safe-in vs boundary
    for (int c = tid; c < nc; c += NTH) {
        const float v = finv(cand_u[c]);
        if (v > vT + dlt) {
            const int slot = atomicAdd(&s_slot, 1);
            if (slot < TOPK) {
                const float zv = fmaxf(v, 0.0f);
                s_tidx[slot] = cand_s[c];
                s_tval[slot] = zv;
                zrow[cand_s[c]] = zv;
            }
        } else if (!full_boundary && v >= vT - dlt) {
            const int p = atomicAdd(&s_nb, 1);
            if (p < 128) s_bidx[p] = cand_s[c];
        }
    }
    if (full_boundary) {
        __syncthreads();
        for (int s = tid; s < D_SAE; s += NTH) {
            const float v = row[s];
            if (v >= vT - dlt && v <= vT + dlt) {
                const int p = atomicAdd(&s_nb, 1);
                if (p < 128) s_bidx[p] = s;
            }
        }
    }
    __syncthreads();
    const int nb = min(s_nb, 128);
    int need = TOPK - s_slot;
    if (need < 0) need = 0;
    if (need > nb) need = nb;

    // exact fp64 pre for boundary candidates (contiguous g_WT rows)
    for (int c = 0; c < nb; c++) {
        const int s = s_bidx[c];
        const float* wrow = g_WT + (size_t)s * KDIM;
        double a = 0.0;
        for (int k = tid; k < KDIM; k += NTH)
            a += (double)s_x[k] * (double)wrow[k];
        s_red[tid] = a;
        __syncthreads();
        for (int st = NTH / 2; st > 0; st >>= 1) {
            if (tid < st) s_red[tid] += s_red[tid + st];
            __syncthreads();
        }
        if (tid == 0) s_exact[c] = s_red[0] + (double)benc[s];
        __syncthreads();
    }

    if (tid == 0) {
        const int base = s_slot;
        for (int r = 0; r < need; r++) {
            int best = -1; double bv = -1e300;
            for (int c = 0; c < nb; c++)
                if (s_exact[c] > bv) { bv = s_exact[c]; best = c; }
            const int s = s_bidx[best];
            const float zv = fmaxf((float)bv, 0.0f);
            s_tidx[base + r] = s;
            s_tval[base + r] = zv;
            zrow[s] = zv;
            s_exact[best] = -1e301;
        }
    }
    __syncthreads();

    // ---- decode: x_hat = sum_k z_k * Wd16[idx_k] + bdec; fused SSE/loss ----
    float acc[9];
#pragma unroll
    for (int i = 0; i < 9; i++) acc[i] = bdec[tid + i * NTH];

    for (int k = 0; k < TOPK; k++) {
        const float v = s_tval[k];
        const __half* w = g_Wd + (size_t)s_tidx[k] * TLD;
#pragma unroll
        for (int i = 0; i < 9; i++)
            acc[i] = fmaf(v, __half2float(w[tid + i * NTH]), acc[i]);
    }

    const float* xb = x + (size_t)b * TLD;
    float* xh = xhat + (size_t)b * TLD;     // 4-byte aligned — scalar only
    float sse = 0.0f;
#pragma unroll
    for (int i = 0; i < 9; i++) {
        const float d = acc[i] - xb[tid + i * NTH];
        sse += d * d;
        xh[tid + i * NTH] = acc[i];
    }

    float* f_red = (float*)s_red;
    f_red[tid] = sse;
    __syncthreads();
    for (int st = NTH / 2; st > 0; st >>= 1) {
        if (tid < st) f_red[tid] += f_red[tid + st];
        __syncthreads();
    }
    if (tid == 0)
        atomicAdd(loss, f_red[0] * (1.0f / (float)(B_SZ * T_SZ * L_SZ)));
}

// ---------------- launch ----------------------------------------------------
extern "C" void kernel_launch(void* const* d_in, const int* in_sizes, int n_in,
                              void* d_out, int out_size)
{
    const float* x    = (const float*)d_in[0];
    const float* Wenc = (const float*)d_in[1];
    const float* benc = (const float*)d_in[2];
    const float* Wdec = (const float*)d_in[3];
    const float* bdec = (const float*)d_in[4];

    float* out  = (float*)d_out;
    float* loss = out;
    float* xhat = out + 1;
    float* z    = out + 1 + (size_t)B_SZ * TLD;

    // 0) W_enc -> g_Bf fp16 [n][k] + g_WT fp32 [n][k] (+ zero loss)
    wsplit_kernel<<<dim3(D_SAE / 32, KDIM / 32), 256>>>(Wenc, loss);
    // 0b) W_dec -> fp16
    wdec_kernel<<<(int)(((size_t)D_SAE * TLD / 4) / 256), 256>>>(Wdec);
    // 1) fold t -> g_xsum + g_Af fp16
    {
        const int n = B_SZ * (KDIM / 2);
        xsum_split_kernel<<<(n + 255) / 256, 256>>>(x);
    }
    // 2) encode GEMM: single-pass fp16 mma.sync
    cudaFuncSetAttribute(encode_gemm_mma,
                         cudaFuncAttributeMaxDynamicSharedMemorySize, SMEM_BYTES);
    encode_gemm_mma<<<dim3(B_SZ / BM, D_SAE / BN), 256, SMEM_BYTES>>>(benc);
    // 3) fused top-64 select (exact via fp64 boundary re-rank) + decode + loss
    cudaFuncSetAttribute(topk_decode_kernel,
                         cudaFuncAttributeMaxDynamicSharedMemorySize, TKD_SMEM);
    topk_decode_kernel<<<B_SZ, NTH, TKD_SMEM>>>(benc, bdec, x, z, xhat, loss);
}